// round 1
// baseline (speedup 1.0000x reference)
#include <cuda_runtime.h>

// Problem shapes (fixed by the dataset)
#define B_ 16
#define N_ 512
#define C_ 384
#define K_ 64
#define NN_ (N_*N_)

// Scratch (no allocs allowed -> __device__ globals)
__device__ float g_attn[B_*K_];                 // [B,K] routing weights
__device__ float g_tm[(size_t)B_*NN_];          // [B,N,N] combined transition
__device__ float g_y[(size_t)B_*N_*C_];         // [B,N,C] pre-projection

// ---------------------------------------------------------------------------
// Kernel 1: mean-pool + L2 normalize + cosine logits + softmax -> g_attn
// One block per batch, 384 threads (one per channel).
// ---------------------------------------------------------------------------
__global__ void attn_kernel(const float* __restrict__ x,
                            const float* __restrict__ centers) {
    int b = blockIdx.x;
    int tid = threadIdx.x;          // 0..383
    __shared__ float s_q[C_];
    __shared__ float s_red[C_];
    __shared__ float s_logit[K_];
    __shared__ float s_mx, s_den;

    // mean over N (coalesced: consecutive threads -> consecutive channels)
    const float* xb = x + (size_t)b * N_ * C_;
    float sum = 0.f;
    for (int n = 0; n < N_; n++) sum += xb[(size_t)n * C_ + tid];
    s_q[tid] = sum * (1.0f / N_);
    __syncthreads();

    // ||q||^2 block reduction (384 = 128*3)
    float v = s_q[tid];
    s_red[tid] = v * v;
    __syncthreads();
    if (tid < 128) s_red[tid] += s_red[tid + 128] + s_red[tid + 256];
    __syncthreads();
    for (int s = 64; s > 0; s >>= 1) {
        if (tid < s) s_red[tid] += s_red[tid + s];
        __syncthreads();
    }
    float qnorm = sqrtf(s_red[0]);

    // cosine logits: thread k (first 64 threads) dots q with centers[:,k]
    if (tid < K_) {
        float dot = 0.f, cs = 0.f;
        #pragma unroll 4
        for (int c = 0; c < C_; c++) {
            float w = centers[(size_t)c * K_ + tid];  // coalesced across k
            dot += s_q[c] * w;
            cs  += w * w;
        }
        float denom = fmaxf(qnorm, 1e-12f) * fmaxf(sqrtf(cs), 1e-12f);
        s_logit[tid] = dot / denom;
    }
    __syncthreads();

    if (tid == 0) {
        float mx = -1e30f;
        for (int k = 0; k < K_; k++) mx = fmaxf(mx, s_logit[k]);
        float den = 0.f;
        for (int k = 0; k < K_; k++) den += expf(s_logit[k] - mx);
        s_mx = mx; s_den = den;
    }
    __syncthreads();
    if (tid < K_) g_attn[b * K_ + tid] = expf(s_logit[tid] - s_mx) / s_den;
}

// ---------------------------------------------------------------------------
// Kernel 2: g_tm[b,n,m] = sum_k attn[b,k] * tran_ms[k,n,m]
// One thread per (n,m); 16 batch accumulators; single pass over tran_ms.
// Memory-bound: 67MB read + 16.8MB write.
// ---------------------------------------------------------------------------
__global__ void tm_kernel(const float* __restrict__ tran) {
    __shared__ float s_attn[B_ * K_];
    int tid = threadIdx.x;                       // 256
    for (int i = tid; i < B_ * K_; i += 256) s_attn[i] = g_attn[i];
    __syncthreads();

    size_t idx = (size_t)blockIdx.x * 256 + tid; // < NN_
    float acc[B_];
    #pragma unroll
    for (int b = 0; b < B_; b++) acc[b] = 0.f;

    #pragma unroll 4
    for (int k = 0; k < K_; k++) {
        float v = tran[(size_t)k * NN_ + idx];
        #pragma unroll
        for (int b = 0; b < B_; b++)
            acc[b] = fmaf(s_attn[b * K_ + k], v, acc[b]);
    }
    #pragma unroll
    for (int b = 0; b < B_; b++)
        g_tm[(size_t)b * NN_ + idx] = acc[b];
}

// ---------------------------------------------------------------------------
// Tiled SGEMM, NN form: C[b] = A[b] @ B[b]
// A [M,K] row-major, B [K,N] row-major. 64x64 tile, BK=16, 256 thr, 4x4/thr.
// ---------------------------------------------------------------------------
#define BM 64
#define BN 64
#define BK 16
#define SPAD 68   // padded smem row stride (floats), keeps float4 alignment

__global__ void gemm_bmm_nn(const float* __restrict__ A,
                            const float* __restrict__ Bm,
                            float* __restrict__ Cm,
                            int M, int Nn, int Kk,
                            size_t strideA, size_t strideB, size_t strideC) {
    __shared__ float As[BK][SPAD];
    __shared__ float Bs[BK][SPAD];

    const float* Ab = A  + (size_t)blockIdx.z * strideA;
    const float* Bb = Bm + (size_t)blockIdx.z * strideB;
    float*       Cb = Cm + (size_t)blockIdx.z * strideC;

    int tid = threadIdx.x;          // 256
    int tx = tid & 15, ty = tid >> 4;
    int n0 = blockIdx.x * BN, m0 = blockIdx.y * BM;

    int a_m = tid >> 2;             // 0..63
    int a_k = (tid & 3) * 4;        // 0,4,8,12
    int b_k = tid >> 4;             // 0..15
    int b_n = (tid & 15) * 4;       // 0..60

    float acc[4][4] = {};

    for (int k0 = 0; k0 < Kk; k0 += BK) {
        float4 av = *(const float4*)(Ab + (size_t)(m0 + a_m) * Kk + k0 + a_k);
        As[a_k + 0][a_m] = av.x;
        As[a_k + 1][a_m] = av.y;
        As[a_k + 2][a_m] = av.z;
        As[a_k + 3][a_m] = av.w;
        *(float4*)(&Bs[b_k][b_n]) =
            *(const float4*)(Bb + (size_t)(k0 + b_k) * Nn + n0 + b_n);
        __syncthreads();

        #pragma unroll
        for (int kk = 0; kk < BK; kk++) {
            float4 a = *(const float4*)(&As[kk][ty * 4]);
            float4 bb = *(const float4*)(&Bs[kk][tx * 4]);
            float ar[4] = {a.x, a.y, a.z, a.w};
            float br[4] = {bb.x, bb.y, bb.z, bb.w};
            #pragma unroll
            for (int i = 0; i < 4; i++)
                #pragma unroll
                for (int j = 0; j < 4; j++)
                    acc[i][j] = fmaf(ar[i], br[j], acc[i][j]);
        }
        __syncthreads();
    }

    #pragma unroll
    for (int i = 0; i < 4; i++) {
        float4 o = make_float4(acc[i][0], acc[i][1], acc[i][2], acc[i][3]);
        *(float4*)(Cb + (size_t)(m0 + ty * 4 + i) * Nn + n0 + tx * 4) = o;
    }
}

// ---------------------------------------------------------------------------
// Tiled SGEMM, NT form with bias: C[m,n] = sum_k A[m,k]*W[n,k] + bias[n]
// A [M,K] row-major, W [N,K] row-major (nn.Linear weight).
// ---------------------------------------------------------------------------
__global__ void gemm_proj_nt(const float* __restrict__ A,
                             const float* __restrict__ W,
                             const float* __restrict__ bias,
                             float* __restrict__ Cm,
                             int M, int Nn, int Kk) {
    __shared__ float As[BK][SPAD];
    __shared__ float Bs[BK][SPAD];

    int tid = threadIdx.x;
    int tx = tid & 15, ty = tid >> 4;
    int n0 = blockIdx.x * BN, m0 = blockIdx.y * BM;

    int a_m = tid >> 2;
    int a_k = (tid & 3) * 4;
    int w_n = tid >> 2;             // 0..63 (output col within tile)
    int w_k = (tid & 3) * 4;        // 0,4,8,12

    float acc[4][4] = {};

    for (int k0 = 0; k0 < Kk; k0 += BK) {
        float4 av = *(const float4*)(A + (size_t)(m0 + a_m) * Kk + k0 + a_k);
        As[a_k + 0][a_m] = av.x;
        As[a_k + 1][a_m] = av.y;
        As[a_k + 2][a_m] = av.z;
        As[a_k + 3][a_m] = av.w;
        float4 wv = *(const float4*)(W + (size_t)(n0 + w_n) * Kk + k0 + w_k);
        Bs[w_k + 0][w_n] = wv.x;
        Bs[w_k + 1][w_n] = wv.y;
        Bs[w_k + 2][w_n] = wv.z;
        Bs[w_k + 3][w_n] = wv.w;
        __syncthreads();

        #pragma unroll
        for (int kk = 0; kk < BK; kk++) {
            float4 a = *(const float4*)(&As[kk][ty * 4]);
            float4 bb = *(const float4*)(&Bs[kk][tx * 4]);
            float ar[4] = {a.x, a.y, a.z, a.w};
            float br[4] = {bb.x, bb.y, bb.z, bb.w};
            #pragma unroll
            for (int i = 0; i < 4; i++)
                #pragma unroll
                for (int j = 0; j < 4; j++)
                    acc[i][j] = fmaf(ar[i], br[j], acc[i][j]);
        }
        __syncthreads();
    }

    float4 bv = *(const float4*)(bias + n0 + tx * 4);
    #pragma unroll
    for (int i = 0; i < 4; i++) {
        float4 o = make_float4(acc[i][0] + bv.x, acc[i][1] + bv.y,
                               acc[i][2] + bv.z, acc[i][3] + bv.w);
        *(float4*)(Cm + (size_t)(m0 + ty * 4 + i) * Nn + n0 + tx * 4) = o;
    }
}

// ---------------------------------------------------------------------------
extern "C" void kernel_launch(void* const* d_in, const int* in_sizes, int n_in,
                              void* d_out, int out_size) {
    const float* x       = (const float*)d_in[0];  // [B,N,C]
    const float* centers = (const float*)d_in[1];  // [C,K]
    const float* tran_ms = (const float*)d_in[2];  // [K,N,N]
    const float* proj_w  = (const float*)d_in[3];  // [C,C]
    const float* proj_b  = (const float*)d_in[4];  // [C]
    float* out = (float*)d_out;                    // [B,N,C]

    float* tm_p;   cudaGetSymbolAddress((void**)&tm_p, g_tm);
    float* y_p;    cudaGetSymbolAddress((void**)&y_p, g_y);

    // 1) routing weights
    attn_kernel<<<B_, C_>>>(x, centers);

    // 2) tm = attn @ tran_ms  (one pass over tran_ms)
    tm_kernel<<<NN_ / 256, 256>>>(tran_ms);

    // 3) y[b] = tm[b] @ x[b]   (M=512, N=384, K=512, batch=16)
    dim3 g1(C_ / BN, N_ / BM, B_);
    gemm_bmm_nn<<<g1, 256>>>(tm_p, x, y_p,
                             N_, C_, N_,
                             (size_t)NN_, (size_t)N_ * C_, (size_t)N_ * C_);

    // 4) out = y @ proj_w^T + proj_b   (M=8192, N=384, K=384)
    dim3 g2(C_ / BN, (B_ * N_) / BM, 1);
    gemm_proj_nt<<<g2, 256>>>(y_p, proj_w, proj_b, out,
                              B_ * N_, C_, C_);
}

// round 2
// speedup vs baseline: 1.2147x; 1.2147x over previous
#include <cuda_runtime.h>

// Problem shapes (fixed by the dataset)
#define B_ 16
#define N_ 512
#define C_ 384
#define K_ 64
#define NN_ (N_*N_)

// Scratch (no allocs allowed -> __device__ globals)
__device__ float g_qpart[B_][8][C_];            // partial mean-pool sums
__device__ float g_attn[B_*K_];                 // [B,K] routing weights
__device__ float g_tm[(size_t)B_*NN_];          // [B,N,N] combined transition
__device__ float g_y[(size_t)B_*N_*C_];         // [B,N,C] pre-projection

// ---------------------------------------------------------------------------
// Kernel 0: parallel partial mean-pool. grid (B,8), 384 threads.
// Each block sums 64 rows of x[b] into g_qpart[b][seg][:].
// ---------------------------------------------------------------------------
__global__ void pool_kernel(const float* __restrict__ x) {
    int b = blockIdx.x, seg = blockIdx.y;
    int c = threadIdx.x;                        // 0..383
    const float* xb = x + (size_t)b * N_ * C_ + (size_t)seg * 64 * C_;
    float s = 0.f;
    #pragma unroll 8
    for (int n = 0; n < 64; n++) s += xb[(size_t)n * C_ + c];
    g_qpart[b][seg][c] = s;
}

// ---------------------------------------------------------------------------
// Kernel 1: finish pool + L2 normalize + cosine logits + softmax -> g_attn
// One block per batch, 384 threads.
// ---------------------------------------------------------------------------
__global__ void attn_kernel(const float* __restrict__ centers) {
    int b = blockIdx.x;
    int tid = threadIdx.x;          // 0..383
    __shared__ float s_q[C_];
    __shared__ float s_red[C_];
    __shared__ float s_logit[K_];
    __shared__ float s_mx, s_den;

    float sum = 0.f;
    #pragma unroll
    for (int seg = 0; seg < 8; seg++) sum += g_qpart[b][seg][tid];
    s_q[tid] = sum * (1.0f / N_);
    __syncthreads();

    float v = s_q[tid];
    s_red[tid] = v * v;
    __syncthreads();
    if (tid < 128) s_red[tid] += s_red[tid + 128] + s_red[tid + 256];
    __syncthreads();
    for (int s = 64; s > 0; s >>= 1) {
        if (tid < s) s_red[tid] += s_red[tid + s];
        __syncthreads();
    }
    float qnorm = sqrtf(s_red[0]);

    if (tid < K_) {
        float dot = 0.f, cs = 0.f;
        #pragma unroll 4
        for (int c = 0; c < C_; c++) {
            float w = centers[(size_t)c * K_ + tid];
            dot += s_q[c] * w;
            cs  += w * w;
        }
        float denom = fmaxf(qnorm, 1e-12f) * fmaxf(sqrtf(cs), 1e-12f);
        s_logit[tid] = dot / denom;
    }
    __syncthreads();

    if (tid == 0) {
        float mx = -1e30f;
        for (int k = 0; k < K_; k++) mx = fmaxf(mx, s_logit[k]);
        float den = 0.f;
        for (int k = 0; k < K_; k++) den += expf(s_logit[k] - mx);
        s_mx = mx; s_den = den;
    }
    __syncthreads();
    if (tid < K_) g_attn[b * K_ + tid] = expf(s_logit[tid] - s_mx) / s_den;
}

// ---------------------------------------------------------------------------
// Kernel 2: g_tm[b,n,m] = sum_k attn[b,k] * tran_ms[k,n,m]
// One thread per (n,m); 16 batch accumulators; single pass over tran_ms.
// ---------------------------------------------------------------------------
__global__ void tm_kernel(const float* __restrict__ tran) {
    __shared__ float s_attn[B_ * K_];
    int tid = threadIdx.x;                       // 256
    for (int i = tid; i < B_ * K_; i += 256) s_attn[i] = g_attn[i];
    __syncthreads();

    size_t idx = (size_t)blockIdx.x * 256 + tid; // < NN_
    float acc[B_];
    #pragma unroll
    for (int b = 0; b < B_; b++) acc[b] = 0.f;

    #pragma unroll 4
    for (int k = 0; k < K_; k++) {
        float v = tran[(size_t)k * NN_ + idx];
        #pragma unroll
        for (int b = 0; b < B_; b++)
            acc[b] = fmaf(s_attn[b * K_ + k], v, acc[b]);
    }
    #pragma unroll
    for (int b = 0; b < B_; b++)
        g_tm[(size_t)b * NN_ + idx] = acc[b];
}

// ---------------------------------------------------------------------------
// GEMM tiles: BM=64, BN=192, BK=16, 256 threads, 4x12 per thread,
// double-buffered smem. Both GEMMs launch exactly 256 CTAs (one wave @ occ2).
// ---------------------------------------------------------------------------
#define BM 64
#define BN 192
#define BK 16
#define ASTR 68    // padded (64+4), rows stay 16B aligned (68*4=272)
#define BSTR_NN 192
#define BSTR_NT 196  // padded for transposed stores (196*4=784, 16B aligned)

// NN: y[b] = tm[b] @ x[b].  A=[512,512] lda=512, B=[512,384] ldb=384.
__global__ __launch_bounds__(256, 2)
void gemm_bmm_nn(const float* __restrict__ A,
                 const float* __restrict__ Bm,
                 float* __restrict__ Cm) {
    __shared__ float As[2][BK][ASTR];
    __shared__ float Bs[2][BK][BSTR_NN];

    int z = blockIdx.z;
    const float* Ab = A  + (size_t)z * NN_;
    const float* Bb = Bm + (size_t)z * N_ * C_;
    float*       Cb = Cm + (size_t)z * N_ * C_;

    int tid = threadIdx.x;
    int m0 = blockIdx.y * BM, n0 = blockIdx.x * BN;
    int ty = tid >> 4, tx = tid & 15;

    int arow = tid >> 2, acol = (tid & 3) << 2;  // A: 64 rows x 16 cols, 1 float4/thr

    // ---- load tile 0 ----
    {
        float4 av = *(const float4*)(Ab + (size_t)(m0 + arow) * 512 + acol);
        As[0][acol + 0][arow] = av.x;
        As[0][acol + 1][arow] = av.y;
        As[0][acol + 2][arow] = av.z;
        As[0][acol + 3][arow] = av.w;
        #pragma unroll
        for (int i = 0; i < 3; i++) {
            int idx = tid + 256 * i;
            int br = idx / 48, bc = (idx % 48) * 4;
            *(float4*)&Bs[0][br][bc] =
                *(const float4*)(Bb + (size_t)br * 384 + n0 + bc);
        }
    }
    __syncthreads();

    float acc[4][12] = {};
    int buf = 0;

    for (int k0 = BK; k0 < 512; k0 += BK) {
        // prefetch next tile into registers
        float4 apre = *(const float4*)(Ab + (size_t)(m0 + arow) * 512 + k0 + acol);
        float4 bpre[3];
        #pragma unroll
        for (int i = 0; i < 3; i++) {
            int idx = tid + 256 * i;
            int br = idx / 48, bc = (idx % 48) * 4;
            bpre[i] = *(const float4*)(Bb + (size_t)(k0 + br) * 384 + n0 + bc);
        }

        // compute on current buffer
        #pragma unroll
        for (int kk = 0; kk < BK; kk++) {
            float a[4], b[12];
            *(float4*)&a[0] = *(const float4*)&As[buf][kk][ty * 4];
            *(float4*)&b[0] = *(const float4*)&Bs[buf][kk][tx * 12];
            *(float4*)&b[4] = *(const float4*)&Bs[buf][kk][tx * 12 + 4];
            *(float4*)&b[8] = *(const float4*)&Bs[buf][kk][tx * 12 + 8];
            #pragma unroll
            for (int i = 0; i < 4; i++)
                #pragma unroll
                for (int j = 0; j < 12; j++)
                    acc[i][j] = fmaf(a[i], b[j], acc[i][j]);
        }

        // store prefetched into other buffer
        As[buf ^ 1][acol + 0][arow] = apre.x;
        As[buf ^ 1][acol + 1][arow] = apre.y;
        As[buf ^ 1][acol + 2][arow] = apre.z;
        As[buf ^ 1][acol + 3][arow] = apre.w;
        #pragma unroll
        for (int i = 0; i < 3; i++) {
            int idx = tid + 256 * i;
            int br = idx / 48, bc = (idx % 48) * 4;
            *(float4*)&Bs[buf ^ 1][br][bc] = bpre[i];
        }
        __syncthreads();
        buf ^= 1;
    }

    // last tile
    #pragma unroll
    for (int kk = 0; kk < BK; kk++) {
        float a[4], b[12];
        *(float4*)&a[0] = *(const float4*)&As[buf][kk][ty * 4];
        *(float4*)&b[0] = *(const float4*)&Bs[buf][kk][tx * 12];
        *(float4*)&b[4] = *(const float4*)&Bs[buf][kk][tx * 12 + 4];
        *(float4*)&b[8] = *(const float4*)&Bs[buf][kk][tx * 12 + 8];
        #pragma unroll
        for (int i = 0; i < 4; i++)
            #pragma unroll
            for (int j = 0; j < 12; j++)
                acc[i][j] = fmaf(a[i], b[j], acc[i][j]);
    }

    #pragma unroll
    for (int i = 0; i < 4; i++) {
        float* crow = Cb + (size_t)(m0 + ty * 4 + i) * 384 + n0 + tx * 12;
        *(float4*)(crow + 0) = make_float4(acc[i][0], acc[i][1], acc[i][2], acc[i][3]);
        *(float4*)(crow + 4) = make_float4(acc[i][4], acc[i][5], acc[i][6], acc[i][7]);
        *(float4*)(crow + 8) = make_float4(acc[i][8], acc[i][9], acc[i][10], acc[i][11]);
    }
}

// NT + bias: out = y @ W^T + b.  A=[8192,384] lda=384, W=[384,384].
__global__ __launch_bounds__(256, 2)
void gemm_proj_nt(const float* __restrict__ A,
                  const float* __restrict__ W,
                  const float* __restrict__ bias,
                  float* __restrict__ Cm) {
    __shared__ float As[2][BK][ASTR];
    __shared__ float Bs[2][BK][BSTR_NT];

    int tid = threadIdx.x;
    int m0 = blockIdx.y * BM, n0 = blockIdx.x * BN;
    int ty = tid >> 4, tx = tid & 15;

    int arow = tid >> 2, acol = (tid & 3) << 2;

    // ---- load tile 0 ----
    {
        float4 av = *(const float4*)(A + (size_t)(m0 + arow) * 384 + acol);
        As[0][acol + 0][arow] = av.x;
        As[0][acol + 1][arow] = av.y;
        As[0][acol + 2][arow] = av.z;
        As[0][acol + 3][arow] = av.w;
        #pragma unroll
        for (int i = 0; i < 3; i++) {
            int idx = tid + 256 * i;
            int wn = idx >> 2, wk = (idx & 3) << 2;
            float4 wv = *(const float4*)(W + (size_t)(n0 + wn) * 384 + wk);
            Bs[0][wk + 0][wn] = wv.x;
            Bs[0][wk + 1][wn] = wv.y;
            Bs[0][wk + 2][wn] = wv.z;
            Bs[0][wk + 3][wn] = wv.w;
        }
    }
    __syncthreads();

    float acc[4][12] = {};
    int buf = 0;

    for (int k0 = BK; k0 < 384; k0 += BK) {
        float4 apre = *(const float4*)(A + (size_t)(m0 + arow) * 384 + k0 + acol);
        float4 bpre[3];
        #pragma unroll
        for (int i = 0; i < 3; i++) {
            int idx = tid + 256 * i;
            int wn = idx >> 2, wk = (idx & 3) << 2;
            bpre[i] = *(const float4*)(W + (size_t)(n0 + wn) * 384 + k0 + wk);
        }

        #pragma unroll
        for (int kk = 0; kk < BK; kk++) {
            float a[4], b[12];
            *(float4*)&a[0] = *(const float4*)&As[buf][kk][ty * 4];
            *(float4*)&b[0] = *(const float4*)&Bs[buf][kk][tx * 12];
            *(float4*)&b[4] = *(const float4*)&Bs[buf][kk][tx * 12 + 4];
            *(float4*)&b[8] = *(const float4*)&Bs[buf][kk][tx * 12 + 8];
            #pragma unroll
            for (int i = 0; i < 4; i++)
                #pragma unroll
                for (int j = 0; j < 12; j++)
                    acc[i][j] = fmaf(a[i], b[j], acc[i][j]);
        }

        As[buf ^ 1][acol + 0][arow] = apre.x;
        As[buf ^ 1][acol + 1][arow] = apre.y;
        As[buf ^ 1][acol + 2][arow] = apre.z;
        As[buf ^ 1][acol + 3][arow] = apre.w;
        #pragma unroll
        for (int i = 0; i < 3; i++) {
            int idx = tid + 256 * i;
            int wn = idx >> 2, wk = (idx & 3) << 2;
            Bs[buf ^ 1][wk + 0][wn] = bpre[i].x;
            Bs[buf ^ 1][wk + 1][wn] = bpre[i].y;
            Bs[buf ^ 1][wk + 2][wn] = bpre[i].z;
            Bs[buf ^ 1][wk + 3][wn] = bpre[i].w;
        }
        __syncthreads();
        buf ^= 1;
    }

    #pragma unroll
    for (int kk = 0; kk < BK; kk++) {
        float a[4], b[12];
        *(float4*)&a[0] = *(const float4*)&As[buf][kk][ty * 4];
        *(float4*)&b[0] = *(const float4*)&Bs[buf][kk][tx * 12];
        *(float4*)&b[4] = *(const float4*)&Bs[buf][kk][tx * 12 + 4];
        *(float4*)&b[8] = *(const float4*)&Bs[buf][kk][tx * 12 + 8];
        #pragma unroll
        for (int i = 0; i < 4; i++)
            #pragma unroll
            for (int j = 0; j < 12; j++)
                acc[i][j] = fmaf(a[i], b[j], acc[i][j]);
    }

    float bv[12];
    *(float4*)&bv[0] = *(const float4*)(bias + n0 + tx * 12);
    *(float4*)&bv[4] = *(const float4*)(bias + n0 + tx * 12 + 4);
    *(float4*)&bv[8] = *(const float4*)(bias + n0 + tx * 12 + 8);

    #pragma unroll
    for (int i = 0; i < 4; i++) {
        float* crow = Cm + (size_t)(m0 + ty * 4 + i) * 384 + n0 + tx * 12;
        *(float4*)(crow + 0) = make_float4(acc[i][0] + bv[0], acc[i][1] + bv[1],
                                           acc[i][2] + bv[2], acc[i][3] + bv[3]);
        *(float4*)(crow + 4) = make_float4(acc[i][4] + bv[4], acc[i][5] + bv[5],
                                           acc[i][6] + bv[6], acc[i][7] + bv[7]);
        *(float4*)(crow + 8) = make_float4(acc[i][8] + bv[8], acc[i][9] + bv[9],
                                           acc[i][10] + bv[10], acc[i][11] + bv[11]);
    }
}

// ---------------------------------------------------------------------------
extern "C" void kernel_launch(void* const* d_in, const int* in_sizes, int n_in,
                              void* d_out, int out_size) {
    const float* x       = (const float*)d_in[0];  // [B,N,C]
    const float* centers = (const float*)d_in[1];  // [C,K]
    const float* tran_ms = (const float*)d_in[2];  // [K,N,N]
    const float* proj_w  = (const float*)d_in[3];  // [C,C]
    const float* proj_b  = (const float*)d_in[4];  // [C]
    float* out = (float*)d_out;                    // [B,N,C]

    float* tm_p;   cudaGetSymbolAddress((void**)&tm_p, g_tm);
    float* y_p;    cudaGetSymbolAddress((void**)&y_p, g_y);

    // 1) routing weights
    pool_kernel<<<dim3(B_, 8), C_>>>(x);
    attn_kernel<<<B_, C_>>>(centers);

    // 2) tm = attn @ tran_ms  (one pass over tran_ms)
    tm_kernel<<<NN_ / 256, 256>>>(tran_ms);

    // 3) y[b] = tm[b] @ x[b]   (M=512, N=384, K=512, batch=16) -> 256 CTAs
    dim3 g1(C_ / BN, N_ / BM, B_);
    gemm_bmm_nn<<<g1, 256>>>(tm_p, x, y_p);

    // 4) out = y @ proj_w^T + proj_b (M=8192, N=384, K=384)    -> 256 CTAs
    dim3 g2(C_ / BN, (B_ * N_) / BM, 1);
    gemm_proj_nt<<<g2, 256>>>(y_p, proj_w, proj_b, out);
}

// round 4
// speedup vs baseline: 1.4009x; 1.1533x over previous
#include <cuda_runtime.h>
#include <cstdint>

// Problem shapes (fixed by the dataset)
#define B_ 16
#define N_ 512
#define C_ 384
#define K_ 64
#define NN_ (N_*N_)

// Scratch (no allocs allowed -> __device__ globals)
__device__ float g_qpart[B_][8][C_];            // partial mean-pool sums
__device__ float g_attn[B_*K_];                 // [B,K] routing weights
__device__ float g_tm[(size_t)B_*NN_];          // [B,N,N] combined transition
__device__ float g_xT[(size_t)B_*C_*N_];        // [B,C,N] transposed x
__device__ float g_y[(size_t)B_*N_*C_];         // [B,N,C] pre-projection

__device__ __forceinline__ float tf32_rnd(float v) {
    uint32_t u;
    asm("cvt.rna.tf32.f32 %0, %1;" : "=r"(u) : "f"(v));
    return __uint_as_float(u);
}
__device__ __forceinline__ void mma_tf32(float* c, const uint32_t* a, const uint32_t* b) {
    asm volatile(
        "mma.sync.aligned.m16n8k8.row.col.f32.tf32.tf32.f32 "
        "{%0,%1,%2,%3}, {%4,%5,%6,%7}, {%8,%9}, {%0,%1,%2,%3};"
        : "+f"(c[0]), "+f"(c[1]), "+f"(c[2]), "+f"(c[3])
        : "r"(a[0]), "r"(a[1]), "r"(a[2]), "r"(a[3]), "r"(b[0]), "r"(b[1]));
}

// ---------------------------------------------------------------------------
// Kernel 0: parallel partial mean-pool. grid (B,8), 384 threads.
// ---------------------------------------------------------------------------
__global__ void pool_kernel(const float* __restrict__ x) {
    int b = blockIdx.x, seg = blockIdx.y;
    int c = threadIdx.x;
    const float* xb = x + (size_t)b * N_ * C_ + (size_t)seg * 64 * C_;
    float s = 0.f;
    #pragma unroll 8
    for (int n = 0; n < 64; n++) s += xb[(size_t)n * C_ + c];
    g_qpart[b][seg][c] = s;
}

// ---------------------------------------------------------------------------
// Kernel 1: finish pool + L2 normalize + cosine logits + softmax -> g_attn
// ---------------------------------------------------------------------------
__global__ void attn_kernel(const float* __restrict__ centers) {
    int b = blockIdx.x;
    int tid = threadIdx.x;
    __shared__ float s_q[C_];
    __shared__ float s_red[C_];
    __shared__ float s_logit[K_];
    __shared__ float s_mx, s_den;

    float sum = 0.f;
    #pragma unroll
    for (int seg = 0; seg < 8; seg++) sum += g_qpart[b][seg][tid];
    s_q[tid] = sum * (1.0f / N_);
    __syncthreads();

    float v = s_q[tid];
    s_red[tid] = v * v;
    __syncthreads();
    if (tid < 128) s_red[tid] += s_red[tid + 128] + s_red[tid + 256];
    __syncthreads();
    for (int s = 64; s > 0; s >>= 1) {
        if (tid < s) s_red[tid] += s_red[tid + s];
        __syncthreads();
    }
    float qnorm = sqrtf(s_red[0]);

    if (tid < K_) {
        float dot = 0.f, cs = 0.f;
        #pragma unroll 4
        for (int c = 0; c < C_; c++) {
            float w = centers[(size_t)c * K_ + tid];
            dot += s_q[c] * w;
            cs  += w * w;
        }
        float denom = fmaxf(qnorm, 1e-12f) * fmaxf(sqrtf(cs), 1e-12f);
        s_logit[tid] = dot / denom;
    }
    __syncthreads();

    if (tid == 0) {
        float mx = -1e30f;
        for (int k = 0; k < K_; k++) mx = fmaxf(mx, s_logit[k]);
        float den = 0.f;
        for (int k = 0; k < K_; k++) den += expf(s_logit[k] - mx);
        s_mx = mx; s_den = den;
    }
    __syncthreads();
    if (tid < K_) g_attn[b * K_ + tid] = expf(s_logit[tid] - s_mx) / s_den;
}

// ---------------------------------------------------------------------------
// Kernel 2: g_tm[b,n,m] = sum_k attn[b,k] * tran_ms[k,n,m] (DRAM-bound)
// ---------------------------------------------------------------------------
__global__ void tm_kernel(const float* __restrict__ tran) {
    __shared__ float s_attn[B_ * K_];
    int tid = threadIdx.x;
    for (int i = tid; i < B_ * K_; i += 256) s_attn[i] = g_attn[i];
    __syncthreads();

    size_t idx = (size_t)blockIdx.x * 256 + tid;
    float acc[B_];
    #pragma unroll
    for (int b = 0; b < B_; b++) acc[b] = 0.f;

    #pragma unroll 4
    for (int k = 0; k < K_; k++) {
        float v = tran[(size_t)k * NN_ + idx];
        #pragma unroll
        for (int b = 0; b < B_; b++)
            acc[b] = fmaf(s_attn[b * K_ + k], v, acc[b]);
    }
    #pragma unroll
    for (int b = 0; b < B_; b++)
        g_tm[(size_t)b * NN_ + idx] = acc[b];
}

// ---------------------------------------------------------------------------
// Kernel 3: transpose x -> xT[b][c][n] = x[b][n][c]
// ---------------------------------------------------------------------------
__global__ void transpose_x(const float* __restrict__ x, float* __restrict__ xT) {
    __shared__ float t[32][33];
    int b = blockIdx.z;
    int n0 = blockIdx.x * 32, c0 = blockIdx.y * 32;
    int tx = threadIdx.x, ty = threadIdx.y;   // 32 x 8
    #pragma unroll
    for (int i = 0; i < 4; i++)
        t[ty + i * 8][tx] = x[(size_t)b * N_ * C_ + (size_t)(n0 + ty + i * 8) * C_ + c0 + tx];
    __syncthreads();
    #pragma unroll
    for (int i = 0; i < 4; i++)
        xT[(size_t)b * C_ * N_ + (size_t)(c0 + ty + i * 8) * N_ + n0 + tx] = t[tx][ty + i * 8];
}

// ---------------------------------------------------------------------------
// Tensor-core GEMM via mma.sync m16n8k8 tf32, 3xTF32 compensated.
// D[m,n] = sum_k A[m,k]*B[n,k] (+bias[n]).
// CTA tile 128x192x32, 8 warps (2x4), warp tile 64x48. 2-stage smem ping-pong.
// Smem XOR swizzle k' = k ^ ((row&7)<<2) -> conflict-free fragment LDS.
// ---------------------------------------------------------------------------
#define TBM 128
#define TBN 192
#define TBK 32
#define A_ELE (TBM*TBK)              // 4096 floats
#define B_ELE (TBN*TBK)              // 6144 floats
#define STAGE_ELE (2*A_ELE + 2*B_ELE)  // 20480 floats = 80KB
#define GSMEM_BYTES (2*STAGE_ELE*4)    // 160KB

__global__ __launch_bounds__(256, 1)
void gemm_mma(const float* __restrict__ A, const float* __restrict__ Bm,
              float* __restrict__ Cm, const float* __restrict__ bias,
              int Kk, int lda, int ldb, int ldc,
              size_t sA, size_t sB, size_t sC) {
    extern __shared__ float sm[];

    const int tid = threadIdx.x;
    const int warp = tid >> 5, lane = tid & 31;
    const int wm = warp >> 2, wn = warp & 3;      // 2 x 4 warp grid
    const int g = lane >> 2, t4 = lane & 3;
    const int swz = g << 2;                        // (row&7)<<2 for all frag rows

    const int m0 = blockIdx.x * TBM, n0 = blockIdx.y * TBN;
    const float* Ab = A  + (size_t)blockIdx.z * sA;
    const float* Bb = Bm + (size_t)blockIdx.z * sB;
    float*       Cb = Cm + (size_t)blockIdx.z * sC;

    // per-thread staging indices for global->smem
    // A: 1024 float4 / 256 thr = 4 ;  B: 1536 / 256 = 6
    float4 aP[4], bP[6];

    auto load_g = [&](int k0) {
        #pragma unroll
        for (int i = 0; i < 4; i++) {
            int f = tid + 256 * i, r = f >> 3, c4 = (f & 7) << 2;
            aP[i] = *(const float4*)(Ab + (size_t)(m0 + r) * lda + k0 + c4);
        }
        #pragma unroll
        for (int i = 0; i < 6; i++) {
            int f = tid + 256 * i, r = f >> 3, c4 = (f & 7) << 2;
            bP[i] = *(const float4*)(Bb + (size_t)(n0 + r) * ldb + k0 + c4);
        }
    };

    auto store_s = [&](int s) {
        float* Ahi = sm + s * STAGE_ELE;
        float* Alo = Ahi + A_ELE;
        float* Bhi = Ahi + 2 * A_ELE;
        float* Blo = Bhi + B_ELE;
        #pragma unroll
        for (int i = 0; i < 4; i++) {
            int f = tid + 256 * i, r = f >> 3, c4 = (f & 7) << 2;
            int off = r * 32 + (c4 ^ ((r & 7) << 2));
            float4 v = aP[i], h, l;
            h.x = tf32_rnd(v.x); l.x = tf32_rnd(v.x - h.x);
            h.y = tf32_rnd(v.y); l.y = tf32_rnd(v.y - h.y);
            h.z = tf32_rnd(v.z); l.z = tf32_rnd(v.z - h.z);
            h.w = tf32_rnd(v.w); l.w = tf32_rnd(v.w - h.w);
            *(float4*)(Ahi + off) = h;
            *(float4*)(Alo + off) = l;
        }
        #pragma unroll
        for (int i = 0; i < 6; i++) {
            int f = tid + 256 * i, r = f >> 3, c4 = (f & 7) << 2;
            int off = r * 32 + (c4 ^ ((r & 7) << 2));
            float4 v = bP[i], h, l;
            h.x = tf32_rnd(v.x); l.x = tf32_rnd(v.x - h.x);
            h.y = tf32_rnd(v.y); l.y = tf32_rnd(v.y - h.y);
            h.z = tf32_rnd(v.z); l.z = tf32_rnd(v.z - h.z);
            h.w = tf32_rnd(v.w); l.w = tf32_rnd(v.w - h.w);
            *(float4*)(Bhi + off) = h;
            *(float4*)(Blo + off) = l;
        }
    };

    float acc[4][6][4];
    #pragma unroll
    for (int mt = 0; mt < 4; mt++)
        #pragma unroll
        for (int nt = 0; nt < 6; nt++)
            #pragma unroll
            for (int q = 0; q < 4; q++) acc[mt][nt][q] = 0.f;

    // precompute row bases (element offsets into 128x32 / 192x32 tiles)
    int arow1[4], brow[6];
    #pragma unroll
    for (int mt = 0; mt < 4; mt++) arow1[mt] = (wm * 64 + mt * 16 + g) * 32;
    #pragma unroll
    for (int nt = 0; nt < 6; nt++) brow[nt] = (wn * 48 + nt * 8 + g) * 32;

    auto compute = [&](int s) {
        const float* Ahi = sm + s * STAGE_ELE;
        const float* Alo = Ahi + A_ELE;
        const float* Bhi = Ahi + 2 * A_ELE;
        const float* Blo = Bhi + B_ELE;
        #pragma unroll
        for (int ks = 0; ks < 4; ks++) {
            const int kx1 = (ks * 8 + t4) ^ swz;
            const int kx2 = (ks * 8 + t4 + 4) ^ swz;
            uint32_t ah[4][4], al[4][4], bh[6][2], bl[6][2];
            #pragma unroll
            for (int mt = 0; mt < 4; mt++) {
                int r1 = arow1[mt], r2 = r1 + 256;   // +8 rows
                ah[mt][0] = __float_as_uint(Ahi[r1 + kx1]);
                ah[mt][1] = __float_as_uint(Ahi[r2 + kx1]);
                ah[mt][2] = __float_as_uint(Ahi[r1 + kx2]);
                ah[mt][3] = __float_as_uint(Ahi[r2 + kx2]);
                al[mt][0] = __float_as_uint(Alo[r1 + kx1]);
                al[mt][1] = __float_as_uint(Alo[r2 + kx1]);
                al[mt][2] = __float_as_uint(Alo[r1 + kx2]);
                al[mt][3] = __float_as_uint(Alo[r2 + kx2]);
            }
            #pragma unroll
            for (int nt = 0; nt < 6; nt++) {
                int rb = brow[nt];
                bh[nt][0] = __float_as_uint(Bhi[rb + kx1]);
                bh[nt][1] = __float_as_uint(Bhi[rb + kx2]);
                bl[nt][0] = __float_as_uint(Blo[rb + kx1]);
                bl[nt][1] = __float_as_uint(Blo[rb + kx2]);
            }
            #pragma unroll
            for (int mt = 0; mt < 4; mt++)
                #pragma unroll
                for (int nt = 0; nt < 6; nt++) {
                    mma_tf32(acc[mt][nt], ah[mt], bh[nt]);
                    mma_tf32(acc[mt][nt], ah[mt], bl[nt]);
                    mma_tf32(acc[mt][nt], al[mt], bh[nt]);
                }
        }
    };

    const int nch = Kk / TBK;
    load_g(0);
    store_s(0);
    __syncthreads();

    int buf = 0;
    for (int ch = 1; ch < nch; ch++) {
        load_g(ch * TBK);
        compute(buf);
        store_s(buf ^ 1);
        __syncthreads();
        buf ^= 1;
    }
    compute(buf);

    // epilogue
    #pragma unroll
    for (int mt = 0; mt < 4; mt++) {
        int row = m0 + wm * 64 + mt * 16 + g;
        #pragma unroll
        for (int nt = 0; nt < 6; nt++) {
            int col = n0 + wn * 48 + nt * 8 + t4 * 2;
            float b0 = 0.f, b1 = 0.f;
            if (bias) { b0 = __ldg(bias + col); b1 = __ldg(bias + col + 1); }
            float* p0 = Cb + (size_t)row * ldc + col;
            float* p1 = Cb + (size_t)(row + 8) * ldc + col;
            *(float2*)p0 = make_float2(acc[mt][nt][0] + b0, acc[mt][nt][1] + b1);
            *(float2*)p1 = make_float2(acc[mt][nt][2] + b0, acc[mt][nt][3] + b1);
        }
    }
}

// ---------------------------------------------------------------------------
extern "C" void kernel_launch(void* const* d_in, const int* in_sizes, int n_in,
                              void* d_out, int out_size) {
    const float* x       = (const float*)d_in[0];  // [B,N,C]
    const float* centers = (const float*)d_in[1];  // [C,K]
    const float* tran_ms = (const float*)d_in[2];  // [K,N,N]
    const float* proj_w  = (const float*)d_in[3];  // [C,C]
    const float* proj_b  = (const float*)d_in[4];  // [C]
    float* out = (float*)d_out;                    // [B,N,C]

    float* tm_p;  cudaGetSymbolAddress((void**)&tm_p, g_tm);
    float* xT_p;  cudaGetSymbolAddress((void**)&xT_p, g_xT);
    float* y_p;   cudaGetSymbolAddress((void**)&y_p, g_y);

    cudaFuncSetAttribute(gemm_mma, cudaFuncAttributeMaxDynamicSharedMemorySize,
                         GSMEM_BYTES);

    // 1) routing weights
    pool_kernel<<<dim3(B_, 8), C_>>>(x);
    attn_kernel<<<B_, C_>>>(centers);

    // 2) xT (B operand for gemm1, K-major)
    transpose_x<<<dim3(N_/32, C_/32, B_), dim3(32, 8)>>>(x, xT_p);

    // 3) tm = attn @ tran_ms
    tm_kernel<<<NN_ / 256, 256>>>(tran_ms);

    // 4) y[b] = tm[b] @ x[b]:  A=tm [512,512], B=xT [384,512]  -> 128 CTAs
    gemm_mma<<<dim3(N_/TBM, C_/TBN, B_), 256, GSMEM_BYTES>>>(
        tm_p, xT_p, y_p, nullptr,
        /*K=*/N_, /*lda=*/N_, /*ldb=*/N_, /*ldc=*/C_,
        (size_t)NN_, (size_t)C_ * N_, (size_t)N_ * C_);

    // 5) out = y @ W^T + b:  A=y [8192,384], B=W [384,384]     -> 128 CTAs
    gemm_mma<<<dim3((B_*N_)/TBM, C_/TBN, 1), 256, GSMEM_BYTES>>>(
        y_p, proj_w, out, proj_b,
        /*K=*/C_, /*lda=*/C_, /*ldb=*/C_, /*ldc=*/C_,
        0, 0, 0);
}